// round 1
// baseline (speedup 1.0000x reference)
#include <cuda_runtime.h>
#include <cuda_bf16.h>
#include <math.h>

// Problem constants
#define BATCH 8
#define HDIM  512
#define WDIM  512
#define NPATCH_SIDE 32           // 512/16
#define NPATCH (NPATCH_SIDE*NPATCH_SIDE)  // 1024
#define PATCH 16
#define NCELL 32
#define GCH   20
#define FEAT  64
#define IMG   (HDIM*WDIM)        // 262144

// Scratch (no allocation allowed)
__device__ float g_ent[BATCH * NPATCH];
__device__ int   g_sel[BATCH];
__device__ float g_loss[BATCH];

// ---------------------------------------------------------------------------
// Kernel 1: per-patch Shannon entropy of grayscale
// grid (1024, 8), block 256 (one thread per pixel of the patch)
// ---------------------------------------------------------------------------
__global__ __launch_bounds__(256) void ent_kernel(const float* __restrict__ HE) {
    const int b = blockIdx.y;
    const int patch = blockIdx.x;
    const int t = threadIdx.x;
    const int y = (patch >> 5) * PATCH + (t >> 4);
    const int x = (patch & 31) * PATCH + (t & 15);

    const size_t base = (size_t)b * 3 * IMG + (size_t)y * WDIM + x;
    const float r  = HE[base];
    const float g  = HE[base + IMG];
    const float bl = HE[base + 2 * IMG];
    const float gray = 0.2989f * r + 0.587f * g + 0.114f * bl;

    __shared__ float s1[256];
    __shared__ float s2[256];
    __shared__ int   hist[256];

    s1[t] = gray;
    s2[t] = gray;
    hist[t] = 0;
    __syncthreads();

    // min / max reduction
    for (int o = 128; o > 0; o >>= 1) {
        if (t < o) {
            s1[t] = fminf(s1[t], s1[t + o]);
            s2[t] = fmaxf(s2[t], s2[t + o]);
        }
        __syncthreads();
    }
    const float mn = s1[0];
    const float mx = s2[0];
    __syncthreads();

    // bin = clip((v*256).astype(int32), 0, 255), v = (x - min)/(max_shifted + 1e-8)
    const float v = (gray - mn) / ((mx - mn) + 1e-8f);
    int bin = (int)(v * 256.0f);
    bin = min(255, max(0, bin));
    atomicAdd(&hist[bin], 1);
    __syncthreads();

    // entropy: -sum p*log2(p), p = c/(256 + 1e-8) == c/256 exactly in f32
    const int c = hist[t];
    float term = 0.0f;
    if (c > 0) {
        const float p = (float)c * (1.0f / 256.0f);
        term = p * log2f(p);
    }
    s1[t] = term;
    __syncthreads();
    for (int o = 128; o > 0; o >>= 1) {
        if (t < o) s1[t] += s1[t + o];
        __syncthreads();
    }
    if (t == 0) g_ent[b * NPATCH + patch] = -s1[0];
}

// ---------------------------------------------------------------------------
// Kernel 2: argmax over 1024 entropies per batch (first-index on ties)
// grid 8, block 1024
// ---------------------------------------------------------------------------
__global__ __launch_bounds__(1024) void argmax_kernel() {
    const int b = blockIdx.x;
    const int t = threadIdx.x;
    __shared__ float sv[1024];
    __shared__ int   si[1024];
    sv[t] = g_ent[b * NPATCH + t];
    si[t] = t;
    __syncthreads();
    for (int o = 512; o > 0; o >>= 1) {
        if (t < o) {
            const float v2 = sv[t + o];
            const int   i2 = si[t + o];
            if (v2 > sv[t] || (v2 == sv[t] && i2 < si[t])) {
                sv[t] = v2;
                si[t] = i2;
            }
        }
        __syncthreads();
    }
    if (t == 0) g_sel[b] = si[0];
}

// ---------------------------------------------------------------------------
// Kernel 3: per-image graph pipeline. grid 8, block 256.
// ---------------------------------------------------------------------------
__global__ __launch_bounds__(256) void per_image_kernel(
    const float* __restrict__ HE, const float* __restrict__ HQ,
    const int* __restrict__ MASK,
    const float* __restrict__ w1, const float* __restrict__ b1,
    const float* __restrict__ w2, const float* __restrict__ b2)
{
    const int b = blockIdx.x;
    const int t = threadIdx.x;
    const int lane = t & 31;
    const int warp = t >> 5;

    __shared__ float Xhe[NCELL][FEAT];   // padded HE features (then standardized)
    __shared__ float Xhq[NCELL][FEAT];
    __shared__ float Ghe[NCELL][FEAT];   // gnn outputs (then standardized)
    __shared__ float Ghq[NCELL][FEAT];
    __shared__ float buf[2048];          // matmul temp, later corr matrices
    __shared__ float adjm[NCELL][NCELL];
    __shared__ float coords[NCELL][2];
    __shared__ float rowsum[NCELL];
    __shared__ float red[256];
    __shared__ float red2[256];
    __shared__ float sc_mux, sc_muy, sc_sx, sc_sy, sc_sxy;

    const int sel = g_sel[b];
    const int y0 = (sel >> 5) * PATCH;
    const int x0 = (sel & 31) * PATCH;

    // zero the padded feature matrices
    for (int i = t; i < NCELL * FEAT; i += 256) {
        ((float*)Xhe)[i] = 0.0f;
        ((float*)Xhq)[i] = 0.0f;
    }
    __syncthreads();

    const float* heb = HE + (size_t)b * 3 * IMG;
    const float* hqb = HQ + (size_t)b * GCH * IMG;
    const int*   mb  = MASK + (size_t)b * NCELL * IMG;

    // ---- per-cell masked stats: each warp handles 4 cells ----
    for (int cell = warp * 4; cell < warp * 4 + 4; cell++) {
        float sm = 0.0f, sx = 0.0f, sy = 0.0f;
        float ehe[3] = {0.0f, 0.0f, 0.0f};
        float ehq[GCH];
        #pragma unroll
        for (int gc = 0; gc < GCH; gc++) ehq[gc] = 0.0f;

        for (int j = 0; j < 8; j++) {
            const int p = lane + 32 * j;
            const int py = p >> 4, px = p & 15;
            const int y = y0 + py, x = x0 + px;
            const float m = (float)mb[((size_t)cell * HDIM + y) * WDIM + x];
            if (m != 0.0f) {
                sm += m;
                sx += m * (float)px;
                sy += m * (float)py;
                const size_t off = (size_t)y * WDIM + x;
                #pragma unroll
                for (int cc = 0; cc < 3; cc++) ehe[cc] += m * heb[(size_t)cc * IMG + off];
                #pragma unroll
                for (int gc = 0; gc < GCH; gc++) ehq[gc] += m * hqb[(size_t)gc * IMG + off];
            }
        }
        // warp reductions
        #pragma unroll
        for (int o = 16; o > 0; o >>= 1) {
            sm += __shfl_down_sync(0xffffffffu, sm, o);
            sx += __shfl_down_sync(0xffffffffu, sx, o);
            sy += __shfl_down_sync(0xffffffffu, sy, o);
            #pragma unroll
            for (int cc = 0; cc < 3; cc++) ehe[cc] += __shfl_down_sync(0xffffffffu, ehe[cc], o);
            #pragma unroll
            for (int gc = 0; gc < GCH; gc++) ehq[gc] += __shfl_down_sync(0xffffffffu, ehq[gc], o);
        }
        if (lane == 0) {
            const float denom = sm + 1e-6f;
            #pragma unroll
            for (int cc = 0; cc < 3; cc++) Xhe[cell][cc] = ehe[cc] / denom;
            #pragma unroll
            for (int gc = 0; gc < GCH; gc++) Xhq[cell][gc] = ehq[gc] / denom;
            coords[cell][0] = sx / sm;   // cnt == sm (mask is 0/1)
            coords[cell][1] = sy / sm;
        }
    }
    __syncthreads();

    // ---- adjacency ----
    for (int i = t; i < NCELL * NCELL; i += 256) {
        const int r_ = i >> 5, c_ = i & 31;
        const float dx = coords[r_][0] - coords[c_][0];
        const float dy = coords[r_][1] - coords[c_][1];
        const float d2 = dx * dx + dy * dy;
        const float dist = sqrtf(fmaxf(d2, 0.0f));
        adjm[r_][c_] = expf(-dist / (3.0f + 1e-6f));
    }
    __syncthreads();
    if (t < NCELL) {
        float s = 0.0f;
        for (int k = 0; k < NCELL; k++) s += adjm[t][k];
        rowsum[t] = s + 1e-8f;
    }
    __syncthreads();
    for (int i = t; i < NCELL * NCELL; i += 256) {
        const int r_ = i >> 5, c_ = i & 31;
        adjm[r_][c_] = adjm[r_][c_] / rowsum[r_];
    }
    __syncthreads();

    // ---- GNN: G = relu((adj @ relu((adj@X)@w1^T + b1)) @ w2^T + b2) ----
    // pass 0: HE features, pass 1: HQ features
    for (int pass = 0; pass < 2; pass++) {
        float (*X)[FEAT] = pass ? Xhq : Xhe;
        float (*G)[FEAT] = pass ? Ghq : Ghe;

        // buf = adj @ X
        for (int i = t; i < NCELL * FEAT; i += 256) {
            const int r_ = i >> 6, c_ = i & 63;
            float acc = 0.0f;
            #pragma unroll
            for (int k = 0; k < NCELL; k++) acc += adjm[r_][k] * X[k][c_];
            buf[i] = acc;
        }
        __syncthreads();
        // G(h) = relu(buf @ w1^T + b1)
        for (int i = t; i < NCELL * FEAT; i += 256) {
            const int r_ = i >> 6, j = i & 63;
            float acc = 0.0f;
            #pragma unroll
            for (int k = 0; k < FEAT; k++) acc += buf[r_ * FEAT + k] * w1[j * FEAT + k];
            G[r_][j] = fmaxf(acc + b1[j], 0.0f);
        }
        __syncthreads();
        // buf = adj @ h
        for (int i = t; i < NCELL * FEAT; i += 256) {
            const int r_ = i >> 6, c_ = i & 63;
            float acc = 0.0f;
            #pragma unroll
            for (int k = 0; k < NCELL; k++) acc += adjm[r_][k] * G[k][c_];
            buf[i] = acc;
        }
        __syncthreads();
        // G = relu(buf @ w2^T + b2)
        for (int i = t; i < NCELL * FEAT; i += 256) {
            const int r_ = i >> 6, j = i & 63;
            float acc = 0.0f;
            #pragma unroll
            for (int k = 0; k < FEAT; k++) acc += buf[r_ * FEAT + k] * w2[j * FEAT + k];
            G[r_][j] = fmaxf(acc + b2[j], 0.0f);
        }
        __syncthreads();
    }

    // ---- standardize columns of [Xhe|Ghe] and [Xhq|Ghq] (over 32 rows, ddof=1) ----
    {
        const int mat = t >> 6;   // 0..3
        const int col = t & 63;
        float (*M)[FEAT] = (mat == 0) ? Xhe : (mat == 1) ? Ghe : (mat == 2) ? Xhq : Ghq;
        float mean = 0.0f;
        #pragma unroll
        for (int r_ = 0; r_ < NCELL; r_++) mean += M[r_][col];
        mean = mean / (float)NCELL;
        float vs = 0.0f;
        #pragma unroll
        for (int r_ = 0; r_ < NCELL; r_++) {
            const float d = M[r_][col] - mean;
            vs += d * d;
        }
        const float sd = sqrtf(vs / (float)(NCELL - 1));
        const float dn = sd + 1e-6f;
        #pragma unroll
        for (int r_ = 0; r_ < NCELL; r_++) M[r_][col] = (M[r_][col] - mean) / dn;
    }
    __syncthreads();

    // ---- correlation matrices: corr = clip(Z @ Z^T / 127, -1, 1) ----
    // buf[0..1023] = corr_he, buf[1024..2047] = corr_hq
    for (int i = t; i < 2048; i += 256) {
        const int half = i >> 10;
        const int idx = i & 1023;
        const int r_ = idx >> 5, c_ = idx & 31;
        float (*X)[FEAT] = half ? Xhq : Xhe;
        float (*G)[FEAT] = half ? Ghq : Ghe;
        float acc = 0.0f;
        #pragma unroll
        for (int k = 0; k < FEAT; k++) acc += X[r_][k] * X[c_][k];
        #pragma unroll
        for (int k = 0; k < FEAT; k++) acc += G[r_][k] * G[c_][k];
        float val = acc / 127.0f;
        val = fminf(1.0f, fmaxf(-1.0f, val));
        buf[i] = val;
    }
    __syncthreads();

    // ---- SSIM(corr_he, corr_hq) over 1024 elements ----
    {
        float px = 0.0f, py = 0.0f;
        for (int i = t; i < 1024; i += 256) {
            px += buf[i];
            py += buf[1024 + i];
        }
        red[t] = px; red2[t] = py;
        __syncthreads();
        for (int o = 128; o > 0; o >>= 1) {
            if (t < o) { red[t] += red[t + o]; red2[t] += red2[t + o]; }
            __syncthreads();
        }
        if (t == 0) {
            sc_mux = red[0] / 1024.0f;
            sc_muy = red2[0] / 1024.0f;
        }
        __syncthreads();
        const float mux = sc_mux, muy = sc_muy;
        float ax = 0.0f, ay = 0.0f, axy = 0.0f;
        for (int i = t; i < 1024; i += 256) {
            const float dx = buf[i] - mux;
            const float dy = buf[1024 + i] - muy;
            ax += dx * dx;
            ay += dy * dy;
            axy += dx * dy;
        }
        red[t] = ax; red2[t] = ay;
        __syncthreads();
        for (int o = 128; o > 0; o >>= 1) {
            if (t < o) { red[t] += red[t + o]; red2[t] += red2[t + o]; }
            __syncthreads();
        }
        if (t == 0) { sc_sx = red[0] / 1023.0f; sc_sy = red2[0] / 1023.0f; }
        __syncthreads();
        red[t] = axy;
        __syncthreads();
        for (int o = 128; o > 0; o >>= 1) {
            if (t < o) red[t] += red[t + o];
            __syncthreads();
        }
        if (t == 0) {
            sc_sxy = red[0] / 1024.0f;
            const float C1 = 1e-4f, C2 = 1e-4f;
            const float num = (2.0f * sc_mux * sc_muy + C1) * (2.0f * sc_sxy + C2);
            const float den = (sc_mux * sc_mux + sc_muy * sc_muy + C1) * (sc_sx + sc_sy + C2);
            float ssim = num / den;
            ssim = fminf(1.0f, fmaxf(0.0f, ssim));
            g_loss[b] = 1.0f - ssim;
        }
    }
}

// ---------------------------------------------------------------------------
// Kernel 4: fixed-order final reduce
// ---------------------------------------------------------------------------
__global__ void final_kernel(float* __restrict__ out) {
    float s = 0.0f;
    #pragma unroll
    for (int i = 0; i < BATCH; i++) s += g_loss[i];
    out[0] = s / (float)BATCH;
}

extern "C" void kernel_launch(void* const* d_in, const int* in_sizes, int n_in,
                              void* d_out, int out_size) {
    (void)in_sizes; (void)n_in; (void)out_size;
    const float* HE   = (const float*)d_in[0];
    const float* HQ   = (const float*)d_in[1];
    const int*   MASK = (const int*)d_in[2];
    const float* w1   = (const float*)d_in[3];
    const float* b1   = (const float*)d_in[4];
    const float* w2   = (const float*)d_in[5];
    const float* b2   = (const float*)d_in[6];

    dim3 g1(NPATCH, BATCH);
    ent_kernel<<<g1, 256>>>(HE);
    argmax_kernel<<<BATCH, 1024>>>();
    per_image_kernel<<<BATCH, 256>>>(HE, HQ, MASK, w1, b1, w2, b2);
    final_kernel<<<1, 1>>>((float*)d_out);
}

// round 2
// speedup vs baseline: 2.6073x; 2.6073x over previous
#include <cuda_runtime.h>
#include <cuda_bf16.h>
#include <math.h>

#define BATCH 8
#define HDIM  512
#define WDIM  512
#define NPATCH 1024
#define PATCH 16
#define NCELL 32
#define GCH   20
#define FEAT  64
#define IMG   (HDIM*WDIM)

// Scratch (no allocation allowed)
__device__ float g_ent[BATCH * NPATCH];
__device__ float g_w1T[FEAT * FEAT];
__device__ float g_w2T[FEAT * FEAT];
__device__ float g_corr[BATCH * 2 * NCELL * NCELL];

// ---------------------------------------------------------------------------
// Kernel 1: per-patch entropy, warp per patch. grid (128, 8), block 256.
// Block (0,0) additionally transposes w1,w2 into global scratch.
// ---------------------------------------------------------------------------
__global__ __launch_bounds__(256) void ent_kernel(
    const float* __restrict__ HE,
    const float* __restrict__ w1, const float* __restrict__ w2)
{
    const int t = threadIdx.x;
    if (blockIdx.x == 0 && blockIdx.y == 0) {
        for (int i = t; i < FEAT * FEAT; i += 256) {
            const int j = i >> 6, k = i & 63;
            g_w1T[k * FEAT + j] = w1[i];
            g_w2T[k * FEAT + j] = w2[i];
        }
    }

    __shared__ int hist[8][256];
    const int warp = t >> 5, lane = t & 31;
    const int p = blockIdx.x * 8 + warp;      // patch index 0..1023
    const int b = blockIdx.y;
    const int y00 = (p >> 5) * PATCH;
    const int x00 = (p & 31) * PATCH;
    const float* base = HE + (size_t)b * 3 * IMG;

    float gv[8];
    #pragma unroll
    for (int j = 0; j < 8; j++) {
        const int idx = lane + 32 * j;
        const int y = y00 + (idx >> 4);
        const int x = x00 + (idx & 15);
        const size_t off = (size_t)y * WDIM + x;
        gv[j] = 0.2989f * base[off] + 0.587f * base[IMG + off] + 0.114f * base[2 * IMG + off];
    }
    float mn = gv[0], mx = gv[0];
    #pragma unroll
    for (int j = 1; j < 8; j++) { mn = fminf(mn, gv[j]); mx = fmaxf(mx, gv[j]); }
    #pragma unroll
    for (int o = 16; o > 0; o >>= 1) {
        mn = fminf(mn, __shfl_xor_sync(0xffffffffu, mn, o));
        mx = fmaxf(mx, __shfl_xor_sync(0xffffffffu, mx, o));
    }

    #pragma unroll
    for (int j = 0; j < 8; j++) hist[warp][lane + 32 * j] = 0;
    __syncwarp();

    const float den = (mx - mn) + 1e-8f;
    #pragma unroll
    for (int j = 0; j < 8; j++) {
        const float v = (gv[j] - mn) / den;     // IEEE division: matches reference
        int bin = (int)(v * 256.0f);
        bin = min(255, max(0, bin));
        atomicAdd(&hist[warp][bin], 1);
    }
    __syncwarp();

    float e = 0.0f;
    #pragma unroll
    for (int j = 0; j < 8; j++) {
        const int c = hist[warp][lane + 32 * j];
        if (c > 0) {
            const float pr = (float)c * (1.0f / 256.0f);
            e += pr * log2f(pr);
        }
    }
    #pragma unroll
    for (int o = 16; o > 0; o >>= 1) e += __shfl_xor_sync(0xffffffffu, e, o);
    if (lane == 0) g_ent[b * NPATCH + p] = -e;
}

// ---------------------------------------------------------------------------
// Kernel 2: argmax + stats + GNN + corr. grid (8 images, 2 passes), block 256.
// ---------------------------------------------------------------------------

// shared pool layout (floats)
#define OFF_X     0            // X[32][65]
#define OFF_ADJ   2080         // adj[32][33]
#define OFF_COORD 3136         // coords[32][2]
#define OFF_ROWS  3200         // rowsum[32]
#define OFF_OV    3328         // overlay: chS (<=5120) | argmax vals | G(2080)+buf(2080)+ws(4224)
#define POOLSZ    11712

template<int NCH>
__device__ __forceinline__ void do_stats(
    const int* __restrict__ mb, const float* chS, float* Xs, float* coordS,
    int lane, int warp, int y0, int x0)
{
    for (int cell = warp * 4; cell < warp * 4 + 4; cell++) {
        float sm = 0.0f, sx = 0.0f, sy = 0.0f;
        float acc[NCH];
        #pragma unroll
        for (int c = 0; c < NCH; c++) acc[c] = 0.0f;

        #pragma unroll
        for (int j = 0; j < 8; j++) {
            const int p = lane + 32 * j;
            const int py = p >> 4, px = p & 15;
            const float m = (float)mb[((size_t)cell * HDIM + y0 + py) * WDIM + x0 + px];
            sm += m;
            sx += m * (float)px;
            sy += m * (float)py;
            #pragma unroll
            for (int c = 0; c < NCH; c++) acc[c] += m * chS[c * 256 + p];
        }
        #pragma unroll
        for (int o = 16; o > 0; o >>= 1) {
            sm += __shfl_down_sync(0xffffffffu, sm, o);
            sx += __shfl_down_sync(0xffffffffu, sx, o);
            sy += __shfl_down_sync(0xffffffffu, sy, o);
            #pragma unroll
            for (int c = 0; c < NCH; c++) acc[c] += __shfl_down_sync(0xffffffffu, acc[c], o);
        }
        if (lane == 0) {
            const float denom = sm + 1e-6f;
            #pragma unroll
            for (int c = 0; c < NCH; c++) Xs[cell * 65 + c] = acc[c] / denom;
            coordS[cell * 2 + 0] = sx / sm;
            coordS[cell * 2 + 1] = sy / sm;
        }
    }
}

__global__ __launch_bounds__(256) void graph_kernel(
    const float* __restrict__ HE, const float* __restrict__ HQ,
    const int* __restrict__ MASK,
    const float* __restrict__ b1, const float* __restrict__ b2)
{
    __shared__ float pool[POOLSZ];
    __shared__ int s_int[257];

    const int b = blockIdx.x;
    const int pass = blockIdx.y;
    const int t = threadIdx.x;
    const int lane = t & 31, warp = t >> 5;

    float* Xs     = pool + OFF_X;      // [32][65]
    float* adjs   = pool + OFF_ADJ;    // [32][33]
    float* coordS = pool + OFF_COORD;  // [32][2]
    float* rowS   = pool + OFF_ROWS;   // [32]
    float* ov     = pool + OFF_OV;

    // ---- argmax over g_ent[b] (first-index on ties) ----
    {
        float bv = -1e30f; int bi = 0;
        for (int i = t; i < NPATCH; i += 256) {
            const float v = g_ent[b * NPATCH + i];
            if (v > bv) { bv = v; bi = i; }   // strided i increasing: first-max kept
        }
        ov[t] = bv; s_int[t] = bi;
        __syncthreads();
        for (int o = 128; o > 0; o >>= 1) {
            if (t < o) {
                const float v2 = ov[t + o]; const int i2 = s_int[t + o];
                if (v2 > ov[t] || (v2 == ov[t] && i2 < s_int[t])) { ov[t] = v2; s_int[t] = i2; }
            }
            __syncthreads();
        }
        if (t == 0) s_int[256] = s_int[0];
        __syncthreads();
    }
    const int sel = s_int[256];
    const int y0 = (sel >> 5) * PATCH;
    const int x0 = (sel & 31) * PATCH;
    __syncthreads();

    // ---- stage channels into shared, zero X ----
    const int nch = pass ? GCH : 3;
    const float* src = pass ? (HQ + (size_t)b * GCH * IMG) : (HE + (size_t)b * 3 * IMG);
    for (int i = t; i < nch * 256; i += 256) {
        const int c = i >> 8, p = i & 255;
        ov[i] = src[(size_t)c * IMG + (size_t)(y0 + (p >> 4)) * WDIM + x0 + (p & 15)];
    }
    for (int i = t; i < 32 * 65; i += 256) Xs[i] = 0.0f;
    __syncthreads();

    // ---- per-cell masked stats ----
    const int* mb = MASK + (size_t)b * NCELL * IMG;
    if (pass == 0) do_stats<3>(mb, ov, Xs, coordS, lane, warp, y0, x0);
    else           do_stats<GCH>(mb, ov, Xs, coordS, lane, warp, y0, x0);
    __syncthreads();

    // ---- adjacency ----
    for (int i = t; i < NCELL * NCELL; i += 256) {
        const int r_ = i >> 5, c_ = i & 31;
        const float dx = coordS[r_ * 2] - coordS[c_ * 2];
        const float dy = coordS[r_ * 2 + 1] - coordS[c_ * 2 + 1];
        const float dist = sqrtf(fmaxf(dx * dx + dy * dy, 0.0f));
        adjs[r_ * 33 + c_] = expf(-dist / 3.000001f);
    }
    __syncthreads();
    if (t < NCELL) {
        float s = 0.0f;
        for (int k = 0; k < NCELL; k++) s += adjs[t * 33 + k];
        rowS[t] = s + 1e-8f;
    }
    __syncthreads();
    for (int i = t; i < NCELL * NCELL; i += 256) {
        const int r_ = i >> 5, c_ = i & 31;
        adjs[r_ * 33 + c_] /= rowS[r_];
    }

    float* Gs   = ov;              // [32][65]
    float* bufS = ov + 2080;       // [32][65]
    float* ws   = ov + 4160;       // [64][66]

    // load w1T into shared
    for (int i = t; i < FEAT * FEAT; i += 256) {
        const int k = i >> 6, j = i & 63;
        ws[k * 66 + j] = g_w1T[i];
    }
    __syncthreads();

    const int rp = t >> 4;               // 0..15 -> rows 2rp, 2rp+1
    const int cg = t & 15;               // cols cg + 16q
    const int r0 = 2 * rp, r1 = r0 + 1;

    // m1: bufS = adj @ X
    {
        float a0q[4] = {0,0,0,0}, a1q[4] = {0,0,0,0};
        #pragma unroll
        for (int k = 0; k < NCELL; k++) {
            const float a0 = adjs[r0 * 33 + k];
            const float a1 = adjs[r1 * 33 + k];
            #pragma unroll
            for (int q = 0; q < 4; q++) {
                const float x = Xs[k * 65 + cg + 16 * q];
                a0q[q] += a0 * x; a1q[q] += a1 * x;
            }
        }
        #pragma unroll
        for (int q = 0; q < 4; q++) {
            bufS[r0 * 65 + cg + 16 * q] = a0q[q];
            bufS[r1 * 65 + cg + 16 * q] = a1q[q];
        }
    }
    __syncthreads();

    // m2: Gs = relu(bufS @ w1^T + b1)
    {
        float a0q[4] = {0,0,0,0}, a1q[4] = {0,0,0,0};
        #pragma unroll
        for (int k = 0; k < FEAT; k++) {
            const float t0 = bufS[r0 * 65 + k];
            const float t1 = bufS[r1 * 65 + k];
            #pragma unroll
            for (int q = 0; q < 4; q++) {
                const float w = ws[k * 66 + cg + 16 * q];
                a0q[q] += t0 * w; a1q[q] += t1 * w;
            }
        }
        #pragma unroll
        for (int q = 0; q < 4; q++) {
            const int j = cg + 16 * q;
            Gs[r0 * 65 + j] = fmaxf(a0q[q] + b1[j], 0.0f);
            Gs[r1 * 65 + j] = fmaxf(a1q[q] + b1[j], 0.0f);
        }
    }
    __syncthreads();

    // m3: bufS = adj @ Gs ; also reload ws = w2T
    {
        float a0q[4] = {0,0,0,0}, a1q[4] = {0,0,0,0};
        #pragma unroll
        for (int k = 0; k < NCELL; k++) {
            const float a0 = adjs[r0 * 33 + k];
            const float a1 = adjs[r1 * 33 + k];
            #pragma unroll
            for (int q = 0; q < 4; q++) {
                const float x = Gs[k * 65 + cg + 16 * q];
                a0q[q] += a0 * x; a1q[q] += a1 * x;
            }
        }
        #pragma unroll
        for (int q = 0; q < 4; q++) {
            bufS[r0 * 65 + cg + 16 * q] = a0q[q];
            bufS[r1 * 65 + cg + 16 * q] = a1q[q];
        }
    }
    __syncthreads();
    for (int i = t; i < FEAT * FEAT; i += 256) {
        const int k = i >> 6, j = i & 63;
        ws[k * 66 + j] = g_w2T[i];
    }
    __syncthreads();

    // m4: Gs = relu(bufS @ w2^T + b2)
    {
        float a0q[4] = {0,0,0,0}, a1q[4] = {0,0,0,0};
        #pragma unroll
        for (int k = 0; k < FEAT; k++) {
            const float t0 = bufS[r0 * 65 + k];
            const float t1 = bufS[r1 * 65 + k];
            #pragma unroll
            for (int q = 0; q < 4; q++) {
                const float w = ws[k * 66 + cg + 16 * q];
                a0q[q] += t0 * w; a1q[q] += t1 * w;
            }
        }
        #pragma unroll
        for (int q = 0; q < 4; q++) {
            const int j = cg + 16 * q;
            Gs[r0 * 65 + j] = fmaxf(a0q[q] + b2[j], 0.0f);
            Gs[r1 * 65 + j] = fmaxf(a1q[q] + b2[j], 0.0f);
        }
    }
    __syncthreads();

    // ---- standardize columns (over 32 rows, ddof=1) ----
    if (t < 128) {
        float* M = (t < 64) ? (Xs + t) : (Gs + (t - 64));
        float mean = 0.0f;
        #pragma unroll
        for (int r_ = 0; r_ < NCELL; r_++) mean += M[r_ * 65];
        mean *= (1.0f / (float)NCELL);
        float vs = 0.0f;
        #pragma unroll
        for (int r_ = 0; r_ < NCELL; r_++) {
            const float d = M[r_ * 65] - mean;
            vs += d * d;
        }
        const float dn = sqrtf(vs / (float)(NCELL - 1)) + 1e-6f;
        #pragma unroll
        for (int r_ = 0; r_ < NCELL; r_++) M[r_ * 65] = (M[r_ * 65] - mean) / dn;
    }
    __syncthreads();

    // ---- corr = clip(Z Z^T / 127, -1, 1) -> global ----
    {
        const int r_ = t >> 3;
        const int cg8 = t & 7;
        float acc[4] = {0, 0, 0, 0};
        #pragma unroll
        for (int k = 0; k < FEAT; k++) {
            const float xr = Xs[r_ * 65 + k];
            #pragma unroll
            for (int q = 0; q < 4; q++) acc[q] += xr * Xs[(cg8 + 8 * q) * 65 + k];
        }
        #pragma unroll
        for (int k = 0; k < FEAT; k++) {
            const float gr = Gs[r_ * 65 + k];
            #pragma unroll
            for (int q = 0; q < 4; q++) acc[q] += gr * Gs[(cg8 + 8 * q) * 65 + k];
        }
        float* dst = g_corr + ((size_t)b * 2 + pass) * (NCELL * NCELL) + r_ * NCELL;
        #pragma unroll
        for (int q = 0; q < 4; q++) {
            float v = acc[q] * (1.0f / 127.0f);
            v = fminf(1.0f, fmaxf(-1.0f, v));
            dst[cg8 + 8 * q] = v;
        }
    }
}

// ---------------------------------------------------------------------------
// Kernel 3: SSIM per image (warp per image) + fixed-order mean. grid 1 x 256.
// ---------------------------------------------------------------------------
__global__ __launch_bounds__(256) void ssim_kernel(float* __restrict__ out) {
    __shared__ float sl[8];
    const int t = threadIdx.x;
    const int lane = t & 31, warp = t >> 5;

    const float* cx = g_corr + (size_t)warp * 2048;
    const float* cy = cx + 1024;

    float sx = 0.0f, sy = 0.0f;
    for (int i = lane; i < 1024; i += 32) { sx += cx[i]; sy += cy[i]; }
    #pragma unroll
    for (int o = 16; o > 0; o >>= 1) {
        sx += __shfl_xor_sync(0xffffffffu, sx, o);
        sy += __shfl_xor_sync(0xffffffffu, sy, o);
    }
    const float mux = sx / 1024.0f;
    const float muy = sy / 1024.0f;

    float ax = 0.0f, ay = 0.0f, axy = 0.0f;
    for (int i = lane; i < 1024; i += 32) {
        const float dx = cx[i] - mux;
        const float dy = cy[i] - muy;
        ax += dx * dx; ay += dy * dy; axy += dx * dy;
    }
    #pragma unroll
    for (int o = 16; o > 0; o >>= 1) {
        ax  += __shfl_xor_sync(0xffffffffu, ax, o);
        ay  += __shfl_xor_sync(0xffffffffu, ay, o);
        axy += __shfl_xor_sync(0xffffffffu, axy, o);
    }
    if (lane == 0) {
        const float vx = ax / 1023.0f, vy = ay / 1023.0f, cxy = axy / 1024.0f;
        const float C1 = 1e-4f, C2 = 1e-4f;
        const float num = (2.0f * mux * muy + C1) * (2.0f * cxy + C2);
        const float den = (mux * mux + muy * muy + C1) * (vx + vy + C2);
        float ssim = num / den;
        ssim = fminf(1.0f, fmaxf(0.0f, ssim));
        sl[warp] = 1.0f - ssim;
    }
    __syncthreads();
    if (t == 0) {
        float s = 0.0f;
        #pragma unroll
        for (int i = 0; i < BATCH; i++) s += sl[i];
        out[0] = s / (float)BATCH;
    }
}

extern "C" void kernel_launch(void* const* d_in, const int* in_sizes, int n_in,
                              void* d_out, int out_size) {
    (void)in_sizes; (void)n_in; (void)out_size;
    const float* HE   = (const float*)d_in[0];
    const float* HQ   = (const float*)d_in[1];
    const int*   MASK = (const int*)d_in[2];
    const float* w1   = (const float*)d_in[3];
    const float* b1   = (const float*)d_in[4];
    const float* w2   = (const float*)d_in[5];
    const float* b2   = (const float*)d_in[6];

    ent_kernel<<<dim3(128, BATCH), 256>>>(HE, w1, w2);
    graph_kernel<<<dim3(BATCH, 2), 256>>>(HE, HQ, MASK, b1, b2);
    ssim_kernel<<<1, 256>>>((float*)d_out);
}

// round 3
// speedup vs baseline: 3.0746x; 1.1792x over previous
#include <cuda_runtime.h>
#include <cuda_bf16.h>
#include <math.h>

#define BATCH 8
#define HDIM  512
#define WDIM  512
#define NPATCH 1024
#define PATCH 16
#define NCELL 32
#define GCH   20
#define FEAT  64
#define IMG   (HDIM*WDIM)

// Scratch (no allocation allowed)
__device__ unsigned long long g_bmax[BATCH * 256];  // per-block packed (entropy, 1023-patch)
__device__ float g_corr[BATCH * 2 * NCELL * NCELL];
__device__ int   g_bar = 0;

// ---------------------------------------------------------------------------
// Kernel 1: per-patch entropy, warp per patch, block = 4 patches.
// grid (256, 8), block 128. Emits per-block argmax candidate (packed u64).
// ---------------------------------------------------------------------------
__global__ __launch_bounds__(128) void ent_kernel(const float* __restrict__ HE) {
    __shared__ int hist[4][256];
    __shared__ unsigned long long keys[4];

    const int t = threadIdx.x, warp = t >> 5, lane = t & 31;
    const int p = blockIdx.x * 4 + warp;
    const int b = blockIdx.y;
    const int y00 = (p >> 5) * PATCH;
    const int x00 = (p & 31) * PATCH;
    const float* base = HE + (size_t)b * 3 * IMG;

    // lane covers 8 pixels: row = lane>>1, col half = (lane&1)*8
    const size_t off = (size_t)(y00 + (lane >> 1)) * WDIM + x00 + (lane & 1) * 8;
    const float4 r0 = *(const float4*)(base + off);
    const float4 r1 = *(const float4*)(base + off + 4);
    const float4 g0 = *(const float4*)(base + IMG + off);
    const float4 g1 = *(const float4*)(base + IMG + off + 4);
    const float4 b0 = *(const float4*)(base + 2 * IMG + off);
    const float4 b1 = *(const float4*)(base + 2 * IMG + off + 4);

    float gv[8];
    gv[0] = 0.2989f * r0.x + 0.587f * g0.x + 0.114f * b0.x;
    gv[1] = 0.2989f * r0.y + 0.587f * g0.y + 0.114f * b0.y;
    gv[2] = 0.2989f * r0.z + 0.587f * g0.z + 0.114f * b0.z;
    gv[3] = 0.2989f * r0.w + 0.587f * g0.w + 0.114f * b0.w;
    gv[4] = 0.2989f * r1.x + 0.587f * g1.x + 0.114f * b1.x;
    gv[5] = 0.2989f * r1.y + 0.587f * g1.y + 0.114f * b1.y;
    gv[6] = 0.2989f * r1.z + 0.587f * g1.z + 0.114f * b1.z;
    gv[7] = 0.2989f * r1.w + 0.587f * g1.w + 0.114f * b1.w;

    float mn = gv[0], mx = gv[0];
    #pragma unroll
    for (int j = 1; j < 8; j++) { mn = fminf(mn, gv[j]); mx = fmaxf(mx, gv[j]); }
    #pragma unroll
    for (int o = 16; o > 0; o >>= 1) {
        mn = fminf(mn, __shfl_xor_sync(0xffffffffu, mn, o));
        mx = fmaxf(mx, __shfl_xor_sync(0xffffffffu, mx, o));
    }

    ((int4*)hist[warp])[lane]      = make_int4(0, 0, 0, 0);
    ((int4*)hist[warp])[lane + 32] = make_int4(0, 0, 0, 0);
    __syncwarp();

    // bin = clip(trunc(((g-mn)/den)*256), 0, 255); fast mul path with exact
    // IEEE-division fallback near bin boundaries (bit-identical bins).
    const float den = (mx - mn) + 1e-8f;
    const float rs = 256.0f / den;
    #pragma unroll
    for (int j = 0; j < 8; j++) {
        const float r = gv[j] - mn;
        const float q = r * rs;
        const float fq = floorf(q);
        int bin;
        const float frac = q - fq;
        if (frac < 5e-4f || frac > 1.0f - 5e-4f) {
            bin = (int)((r / den) * 256.0f);      // exact reference path
        } else {
            bin = (int)fq;
        }
        bin = min(255, max(0, bin));
        atomicAdd(&hist[warp][bin], 1);
    }
    __syncwarp();

    // entropy from counts (p = c/256 exact)
    const int4 c0 = ((const int4*)hist[warp])[lane];
    const int4 c1 = ((const int4*)hist[warp])[lane + 32];
    float e = 0.0f;
    {
        const int cs[8] = {c0.x, c0.y, c0.z, c0.w, c1.x, c1.y, c1.z, c1.w};
        #pragma unroll
        for (int j = 0; j < 8; j++) {
            if (cs[j] > 0) {
                const float pr = (float)cs[j] * (1.0f / 256.0f);
                e += pr * log2f(pr);
            }
        }
    }
    #pragma unroll
    for (int o = 16; o > 0; o >>= 1) e += __shfl_xor_sync(0xffffffffu, e, o);

    const float ent = fmaxf(-e, 0.0f);  // avoid -0.0 breaking bit-monotonic pack
    const unsigned long long key =
        ((unsigned long long)__float_as_uint(ent) << 32) | (unsigned)(NPATCH - 1 - p);
    if (lane == 0) keys[warp] = key;
    __syncthreads();
    if (t == 0) {
        unsigned long long k = keys[0];
        #pragma unroll
        for (int w = 1; w < 4; w++) k = (keys[w] > k) ? keys[w] : k;
        g_bmax[b * 256 + blockIdx.x] = k;
    }
}

// ---------------------------------------------------------------------------
// Kernel 2: argmax + stats + GNN + corr (+ fused SSIM in block (0,0)).
// grid (8 images, 2 passes), block 512.
// ---------------------------------------------------------------------------

// shared pool layout (floats)
#define OFF_X     0            // X[32][65]
#define OFF_ADJ   2080         // adj[32][33]
#define OFF_COORD 3136         // coords[32][2]
#define OFF_ROWS  3200         // rowsum[32]
#define OFF_OV    3328         // overlay: chS(<=5120) | G(2080)+buf(2080)+ws(4224)
#define POOLSZ    11712

template<int NCH>
__device__ __forceinline__ void do_stats(
    const int* __restrict__ mb, const float* chS, float* Xs, float* coordS,
    int lane, int warp, int y0, int x0)
{
    for (int cell = warp * 2; cell < warp * 2 + 2; cell++) {
        float sm = 0.0f, sx = 0.0f, sy = 0.0f;
        float acc[NCH];
        #pragma unroll
        for (int c = 0; c < NCH; c++) acc[c] = 0.0f;

        #pragma unroll
        for (int j = 0; j < 8; j++) {
            const int p = lane + 32 * j;
            const int py = p >> 4, px = p & 15;
            const float m = (float)mb[((size_t)cell * HDIM + y0 + py) * WDIM + x0 + px];
            sm += m;
            sx += m * (float)px;
            sy += m * (float)py;
            #pragma unroll
            for (int c = 0; c < NCH; c++) acc[c] += m * chS[c * 256 + p];
        }
        #pragma unroll
        for (int o = 16; o > 0; o >>= 1) {
            sm += __shfl_down_sync(0xffffffffu, sm, o);
            sx += __shfl_down_sync(0xffffffffu, sx, o);
            sy += __shfl_down_sync(0xffffffffu, sy, o);
            #pragma unroll
            for (int c = 0; c < NCH; c++) acc[c] += __shfl_down_sync(0xffffffffu, acc[c], o);
        }
        if (lane == 0) {
            const float denom = sm + 1e-6f;
            #pragma unroll
            for (int c = 0; c < NCH; c++) Xs[cell * 65 + c] = acc[c] / denom;
            coordS[cell * 2 + 0] = sx / sm;
            coordS[cell * 2 + 1] = sy / sm;
        }
    }
}

__global__ __launch_bounds__(512) void graph_kernel(
    const float* __restrict__ HE, const float* __restrict__ HQ,
    const int* __restrict__ MASK,
    const float* __restrict__ w1, const float* __restrict__ b1,
    const float* __restrict__ w2, const float* __restrict__ b2,
    float* __restrict__ out)
{
    __shared__ float pool[POOLSZ];
    __shared__ int s_sel;

    const int b = blockIdx.x;
    const int pass = blockIdx.y;
    const int t = threadIdx.x;
    const int lane = t & 31, warp = t >> 5;

    float* Xs     = pool + OFF_X;
    float* adjs   = pool + OFF_ADJ;
    float* coordS = pool + OFF_COORD;
    float* rowS   = pool + OFF_ROWS;
    float* ov     = pool + OFF_OV;

    // ---- argmax over 256 per-block candidates (warp 0) ----
    if (t < 32) {
        unsigned long long k = 0ull;
        #pragma unroll
        for (int j = 0; j < 8; j++) {
            const unsigned long long v = g_bmax[b * 256 + t + 32 * j];
            k = (v > k) ? v : k;
        }
        #pragma unroll
        for (int o = 16; o > 0; o >>= 1) {
            const unsigned long long v = __shfl_xor_sync(0xffffffffu, k, o);
            k = (v > k) ? v : k;
        }
        if (t == 0) s_sel = NPATCH - 1 - (int)(unsigned)(k & 0xffffffffu);
    }
    __syncthreads();
    const int sel = s_sel;
    const int y0 = (sel >> 5) * PATCH;
    const int x0 = (sel & 31) * PATCH;

    // ---- stage channels into shared, zero X ----
    const int nch = pass ? GCH : 3;
    const float* src = pass ? (HQ + (size_t)b * GCH * IMG) : (HE + (size_t)b * 3 * IMG);
    for (int i = t; i < nch * 256; i += 512) {
        const int c = i >> 8, p = i & 255;
        ov[i] = src[(size_t)c * IMG + (size_t)(y0 + (p >> 4)) * WDIM + x0 + (p & 15)];
    }
    for (int i = t; i < 32 * 65; i += 512) Xs[i] = 0.0f;
    __syncthreads();

    // ---- per-cell masked stats (16 warps x 2 cells) ----
    const int* mb = MASK + (size_t)b * NCELL * IMG;
    if (pass == 0) do_stats<3>(mb, ov, Xs, coordS, lane, warp, y0, x0);
    else           do_stats<GCH>(mb, ov, Xs, coordS, lane, warp, y0, x0);
    __syncthreads();

    // ---- adjacency ----
    for (int i = t; i < NCELL * NCELL; i += 512) {
        const int r_ = i >> 5, c_ = i & 31;
        const float dx = coordS[r_ * 2] - coordS[c_ * 2];
        const float dy = coordS[r_ * 2 + 1] - coordS[c_ * 2 + 1];
        const float dist = sqrtf(fmaxf(dx * dx + dy * dy, 0.0f));
        adjs[r_ * 33 + c_] = expf(-dist / 3.000001f);
    }
    __syncthreads();
    if (t < NCELL) {
        float s = 0.0f;
        #pragma unroll
        for (int k = 0; k < NCELL; k++) s += adjs[t * 33 + k];
        rowS[t] = s + 1e-8f;
    }
    __syncthreads();
    for (int i = t; i < NCELL * NCELL; i += 512) {
        const int r_ = i >> 5, c_ = i & 31;
        adjs[r_ * 33 + c_] /= rowS[r_];
    }

    float* Gs   = ov;              // [32][65]
    float* bufS = ov + 2080;       // [32][65]
    float* ws   = ov + 4160;       // [64][66]

    // ws = w1^T (transposed load straight from global)
    for (int i = t; i < FEAT * FEAT; i += 512)
        ws[(i & 63) * 66 + (i >> 6)] = w1[i];
    __syncthreads();

    const int r_ = t >> 4;          // 0..31
    const int cg = t & 15;          // cols cg + 16q

    // m1: bufS = adj @ X
    {
        float aq[4] = {0, 0, 0, 0};
        #pragma unroll
        for (int k = 0; k < NCELL; k++) {
            const float a = adjs[r_ * 33 + k];
            #pragma unroll
            for (int q = 0; q < 4; q++) aq[q] += a * Xs[k * 65 + cg + 16 * q];
        }
        #pragma unroll
        for (int q = 0; q < 4; q++) bufS[r_ * 65 + cg + 16 * q] = aq[q];
    }
    __syncthreads();

    // m2: Gs = relu(bufS @ w1^T + b1)
    {
        float aq[4] = {0, 0, 0, 0};
        #pragma unroll
        for (int k = 0; k < FEAT; k++) {
            const float tv = bufS[r_ * 65 + k];
            #pragma unroll
            for (int q = 0; q < 4; q++) aq[q] += tv * ws[k * 66 + cg + 16 * q];
        }
        #pragma unroll
        for (int q = 0; q < 4; q++) {
            const int j = cg + 16 * q;
            Gs[r_ * 65 + j] = fmaxf(aq[q] + b1[j], 0.0f);
        }
    }
    __syncthreads();

    // m3: bufS = adj @ Gs
    {
        float aq[4] = {0, 0, 0, 0};
        #pragma unroll
        for (int k = 0; k < NCELL; k++) {
            const float a = adjs[r_ * 33 + k];
            #pragma unroll
            for (int q = 0; q < 4; q++) aq[q] += a * Gs[k * 65 + cg + 16 * q];
        }
        #pragma unroll
        for (int q = 0; q < 4; q++) bufS[r_ * 65 + cg + 16 * q] = aq[q];
    }
    __syncthreads();
    // ws = w2^T
    for (int i = t; i < FEAT * FEAT; i += 512)
        ws[(i & 63) * 66 + (i >> 6)] = w2[i];
    __syncthreads();

    // m4: Gs = relu(bufS @ w2^T + b2)
    {
        float aq[4] = {0, 0, 0, 0};
        #pragma unroll
        for (int k = 0; k < FEAT; k++) {
            const float tv = bufS[r_ * 65 + k];
            #pragma unroll
            for (int q = 0; q < 4; q++) aq[q] += tv * ws[k * 66 + cg + 16 * q];
        }
        #pragma unroll
        for (int q = 0; q < 4; q++) {
            const int j = cg + 16 * q;
            Gs[r_ * 65 + j] = fmaxf(aq[q] + b2[j], 0.0f);
        }
    }
    __syncthreads();

    // ---- standardize columns (over 32 rows, ddof=1) ----
    if (t < 128) {
        float* M = (t < 64) ? (Xs + t) : (Gs + (t - 64));
        float mean = 0.0f;
        #pragma unroll
        for (int rr = 0; rr < NCELL; rr++) mean += M[rr * 65];
        mean *= (1.0f / (float)NCELL);
        float vs = 0.0f;
        #pragma unroll
        for (int rr = 0; rr < NCELL; rr++) {
            const float d = M[rr * 65] - mean;
            vs += d * d;
        }
        const float dn = sqrtf(vs / (float)(NCELL - 1)) + 1e-6f;
        #pragma unroll
        for (int rr = 0; rr < NCELL; rr++) M[rr * 65] = (M[rr * 65] - mean) / dn;
    }
    __syncthreads();

    // ---- corr = clip(Z Z^T / 127, -1, 1) -> global ----
    {
        float acc[2] = {0, 0};
        #pragma unroll
        for (int k = 0; k < FEAT; k++) {
            const float xr = Xs[r_ * 65 + k];
            #pragma unroll
            for (int q = 0; q < 2; q++) acc[q] += xr * Xs[(cg + 16 * q) * 65 + k];
        }
        #pragma unroll
        for (int k = 0; k < FEAT; k++) {
            const float gr = Gs[r_ * 65 + k];
            #pragma unroll
            for (int q = 0; q < 2; q++) acc[q] += gr * Gs[(cg + 16 * q) * 65 + k];
        }
        float* dst = g_corr + ((size_t)b * 2 + pass) * (NCELL * NCELL) + r_ * NCELL;
        #pragma unroll
        for (int q = 0; q < 2; q++) {
            float v = acc[q] * (1.0f / 127.0f);
            v = fminf(1.0f, fmaxf(-1.0f, v));
            dst[cg + 16 * q] = v;
        }
    }

    // ---- inter-block barrier (16 co-resident blocks) ----
    __threadfence();
    __syncthreads();
    if (t == 0) atomicAdd(&g_bar, 1);
    if (b != 0 || pass != 0) return;

    if (t == 0) {
        volatile int* vb = &g_bar;
        while (*vb < 16) { }
    }
    __syncthreads();
    __threadfence();

    // ---- fused SSIM: warp w -> image w (warps 0..7) + fixed-order mean ----
    float* sl = pool;   // reuse
    if (warp < BATCH) {
        const float* cx = g_corr + (size_t)warp * 2048;
        const float* cy = cx + 1024;
        float sx = 0.0f, sy = 0.0f;
        for (int i = lane; i < 1024; i += 32) { sx += cx[i]; sy += cy[i]; }
        #pragma unroll
        for (int o = 16; o > 0; o >>= 1) {
            sx += __shfl_xor_sync(0xffffffffu, sx, o);
            sy += __shfl_xor_sync(0xffffffffu, sy, o);
        }
        const float mux = sx / 1024.0f;
        const float muy = sy / 1024.0f;
        float ax = 0.0f, ay = 0.0f, axy = 0.0f;
        for (int i = lane; i < 1024; i += 32) {
            const float dx = cx[i] - mux;
            const float dy = cy[i] - muy;
            ax += dx * dx; ay += dy * dy; axy += dx * dy;
        }
        #pragma unroll
        for (int o = 16; o > 0; o >>= 1) {
            ax  += __shfl_xor_sync(0xffffffffu, ax, o);
            ay  += __shfl_xor_sync(0xffffffffu, ay, o);
            axy += __shfl_xor_sync(0xffffffffu, axy, o);
        }
        if (lane == 0) {
            const float vx = ax / 1023.0f, vy = ay / 1023.0f, cxy = axy / 1024.0f;
            const float C1 = 1e-4f, C2 = 1e-4f;
            const float num = (2.0f * mux * muy + C1) * (2.0f * cxy + C2);
            const float den = (mux * mux + muy * muy + C1) * (vx + vy + C2);
            float ssim = num / den;
            ssim = fminf(1.0f, fmaxf(0.0f, ssim));
            sl[warp] = 1.0f - ssim;
        }
    }
    __syncthreads();
    if (t == 0) {
        float s = 0.0f;
        #pragma unroll
        for (int i = 0; i < BATCH; i++) s += sl[i];
        out[0] = s / (float)BATCH;
        g_bar = 0;   // reset for next replay (visible at kernel boundary)
    }
}

extern "C" void kernel_launch(void* const* d_in, const int* in_sizes, int n_in,
                              void* d_out, int out_size) {
    (void)in_sizes; (void)n_in; (void)out_size;
    const float* HE   = (const float*)d_in[0];
    const float* HQ   = (const float*)d_in[1];
    const int*   MASK = (const int*)d_in[2];
    const float* w1   = (const float*)d_in[3];
    const float* b1   = (const float*)d_in[4];
    const float* w2   = (const float*)d_in[5];
    const float* b2   = (const float*)d_in[6];

    ent_kernel<<<dim3(256, BATCH), 128>>>(HE);
    graph_kernel<<<dim3(BATCH, 2), 512>>>(HE, HQ, MASK, w1, b1, w2, b2, (float*)d_out);
}